// round 15
// baseline (speedup 1.0000x reference)
#include <cuda_runtime.h>
#include <cuda_fp16.h>
#include <cstdint>

#define B_ 4
#define S_ 2048
#define D_ 512
#define TOK (B_*S_)

// ------------------------- device scratch ---------------------------------
__device__ __half g_x_fh[TOK*D_], g_x_fl[TOK*D_];     // x fp16 hi/lo
__device__ __half g_w_f[4*D_*D_];                     // W single fp16, [n][k]
__device__ __half g_q_f[TOK*D_];                      // Q fp16, prescaled by log2(e)/8
__device__ __half g_k_f[TOK*D_];                      // K fp16
__device__ __half g_vt_f[TOK*D_];                     // V fp16, [b,h,d,S]
__device__ __half g_att_f[TOK*D_];                    // attn out fp16 single

// ------------------------- PTX helpers ------------------------------------
__device__ __forceinline__ uint32_t smem_u32(const void* p) {
    uint32_t a;
    asm("{ .reg .u64 t; cvta.to.shared.u64 t, %1; cvt.u32.u64 %0, t; }"
        : "=r"(a) : "l"(p));
    return a;
}
#define CP_ASYNC(d, s) asm volatile("cp.async.cg.shared.global [%0], [%1], 16;" :: "r"(d), "l"(s) : "memory")
#define CP_COMMIT()    asm volatile("cp.async.commit_group;" ::: "memory")
#define CP_WAIT(n)     asm volatile("cp.async.wait_group %0;" :: "n"(n) : "memory")

__device__ __forceinline__ void ldsm4(uint32_t* r, uint32_t a) {
    asm volatile("ldmatrix.sync.aligned.m8n8.x4.shared.b16 {%0,%1,%2,%3}, [%4];"
        : "=r"(r[0]), "=r"(r[1]), "=r"(r[2]), "=r"(r[3]) : "r"(a));
}
__device__ __forceinline__ void mma16816h(float* c, const uint32_t* a, const uint32_t* b) {
    asm volatile("mma.sync.aligned.m16n8k16.row.col.f32.f16.f16.f32 "
        "{%0,%1,%2,%3}, {%4,%5,%6,%7}, {%8,%9}, {%0,%1,%2,%3};"
        : "+f"(c[0]), "+f"(c[1]), "+f"(c[2]), "+f"(c[3])
        : "r"(a[0]), "r"(a[1]), "r"(a[2]), "r"(a[3]), "r"(b[0]), "r"(b[1]));
}
__device__ __forceinline__ float fast_ex2(float x) {
    float y; asm("ex2.approx.f32 %0, %1;" : "=f"(y) : "f"(x)); return y;
}
__device__ __forceinline__ void split2h(float f0, float f1, uint32_t& h, uint32_t& l) {
    __half h0 = __float2half_rn(f0), h1 = __float2half_rn(f1);
    __half l0 = __float2half_rn(f0 - __half2float(h0));
    __half l1 = __float2half_rn(f1 - __half2float(h1));
    __half2 th = __halves2half2(h0, h1), tl = __halves2half2(l0, l1);
    h = *reinterpret_cast<uint32_t*>(&th);
    l = *reinterpret_cast<uint32_t*>(&tl);
}
__device__ __forceinline__ uint32_t pack2h(float x, float y) {
    __half2 t = __floats2half2_rn(x, y);
    return *reinterpret_cast<uint32_t*>(&t);
}
// 64 strided floats (scaled) -> 64 fp16
__device__ __forceinline__ void row64_h(const float* src, int stride, float scale, __half* o) {
#pragma unroll
    for (int g = 0; g < 8; g++) {
        uint32_t hh[4];
#pragma unroll
        for (int p = 0; p < 4; p++)
            hh[p] = pack2h(src[(g*8 + p*2) * stride] * scale,
                           src[(g*8 + p*2 + 1) * stride] * scale);
        *reinterpret_cast<uint4*>(o + g*8) = make_uint4(hh[0], hh[1], hh[2], hh[3]);
    }
}

// ------------------------- prep kernels -----------------------------------
__global__ __launch_bounds__(256) void cvt_x(const float* __restrict__ x) {
    size_t i = ((size_t)blockIdx.x * 256 + threadIdx.x) * 4;
    float4 v = *reinterpret_cast<const float4*>(x + i);
    uint32_t h0, l0, h1, l1;
    split2h(v.x, v.y, h0, l0);
    split2h(v.z, v.w, h1, l1);
    *reinterpret_cast<uint2*>(g_x_fh + i) = make_uint2(h0, h1);
    *reinterpret_cast<uint2*>(g_x_fl + i) = make_uint2(l0, l1);
}

__global__ __launch_bounds__(256) void cvt_w(const float* __restrict__ Wq,
                                             const float* __restrict__ Wk,
                                             const float* __restrict__ Wv,
                                             const float* __restrict__ Wo) {
    __shared__ float t[32][33];
    const int z = blockIdx.z;
    const float* W = (z == 0) ? Wq : (z == 1) ? Wk : (z == 2) ? Wv : Wo;
    const int k0 = blockIdx.x * 32, n0 = blockIdx.y * 32;
    const int tx = threadIdx.x & 31, ty = threadIdx.x >> 5;
#pragma unroll
    for (int r = 0; r < 4; r++)
        t[ty + r * 8][tx] = W[(size_t)(k0 + ty + r * 8) * D_ + n0 + tx];
    __syncthreads();
#pragma unroll
    for (int r = 0; r < 4; r++) {
        int nn = ty + r * 8;
        size_t oi = (size_t)z * D_ * D_ + (size_t)(n0 + nn) * D_ + k0 + tx;
        g_w_f[oi] = __float2half_rn(t[tx][nn]);
    }
}

// ------------------------- HMMA GEMM --------------------------------------
// C = A @ W. TWOPASS: A fp16 hi/lo (x). !TWOPASS: A single fp16 (att).
// Block 128x128, warp 64x32, k=32. modes: 0=Q(prescaled) 1=K 2=V(T) 3=O
#define GSM 67584
#define CEXP 0.18033688011112042f   /* log2(e)/8 */

template <bool TWOPASS>
__global__ __launch_bounds__(256, 2) void gemm_mma(int mode_base,
                                                   const float* __restrict__ bias,
                                                   float* __restrict__ out) {
    extern __shared__ char sm[];
    const int tid = threadIdx.x, lane = tid & 31, w = tid >> 5;
    const int wm = w & 1, wn = w >> 1;
    const int mode = mode_base + blockIdx.z;
    const int m0 = blockIdx.x * 128, n0 = blockIdx.y * 128;
    const uint32_t sb = smem_u32(sm);

    const __half* Ah = (TWOPASS ? g_x_fh : g_att_f) + (size_t)m0 * D_;
    const __half* Al = g_x_fl + (size_t)m0 * D_;
    const __half* Bf = g_w_f + (size_t)mode * D_ * D_ + (size_t)n0 * D_;

    float acc[4][4][4];
#pragma unroll
    for (int i = 0; i < 4; i++)
#pragma unroll
        for (int j = 0; j < 4; j++)
#pragma unroll
            for (int k = 0; k < 4; k++) acc[i][j][k] = 0.f;

    const int lr = tid >> 1, half = tid & 1;
    auto load_chunk = [&](int buf, int k0) {
        uint32_t d = sb + buf * 30720 + lr * 80 + half * 32;
        const size_t so = (size_t)lr * D_ + k0 + half * 16;
#pragma unroll
        for (int j = 0; j < 2; j++) {
            CP_ASYNC(d + j * 16, Ah + so + j * 8);
            if (TWOPASS) CP_ASYNC(d + 10240 + j * 16, Al + so + j * 8);
            CP_ASYNC(d + 20480 + j * 16, Bf + so + j * 8);
        }
    };

    load_chunk(0, 0); CP_COMMIT();
    const uint32_t arow = (uint32_t)(wm * 64 + (lane & 15)) * 80 + (lane >> 4) * 16;
    const uint32_t brow = (uint32_t)(wn * 32 + ((lane >> 4) & 1) * 8 + (lane & 7)) * 80
                          + ((lane >> 3) & 1) * 16;

    for (int c = 0; c < 16; c++) {
        if (c < 15) { load_chunk((c + 1) & 1, (c + 1) * 32); CP_COMMIT(); CP_WAIT(1); }
        else CP_WAIT(0);
        __syncthreads();
        const uint32_t base = sb + (c & 1) * 30720;
#pragma unroll
        for (int kk = 0; kk < 2; kk++) {
            uint32_t bh[2][4];
#pragma unroll
            for (int nt2 = 0; nt2 < 2; nt2++)
                ldsm4(bh[nt2], base + 20480 + brow + nt2 * 16 * 80 + kk * 32);
#pragma unroll
            for (int mt = 0; mt < 4; mt++) {
                uint32_t aa = base + arow + mt * 16 * 80 + kk * 32;
                uint32_t ah[4], al[4];
                ldsm4(ah, aa);
                if (TWOPASS) ldsm4(al, aa + 10240);
#pragma unroll
                for (int nt2 = 0; nt2 < 2; nt2++) {
                    mma16816h(acc[mt][nt2 * 2],     ah, &bh[nt2][0]);
                    if (TWOPASS) mma16816h(acc[mt][nt2 * 2], al, &bh[nt2][0]);
                    mma16816h(acc[mt][nt2 * 2 + 1], ah, &bh[nt2][2]);
                    if (TWOPASS) mma16816h(acc[mt][nt2 * 2 + 1], al, &bh[nt2][2]);
                }
            }
        }
        __syncthreads();
    }

    // stage C into smem [128][132] f32
    float* cs = reinterpret_cast<float*>(sm);
    {
        const int rr = wm * 64 + (lane >> 2), cc = wn * 32 + 2 * (lane & 3);
#pragma unroll
        for (int mt = 0; mt < 4; mt++)
#pragma unroll
            for (int nt = 0; nt < 4; nt++) {
                int r0 = rr + mt * 16, c0 = cc + nt * 8;
                cs[r0 * 132 + c0]           = acc[mt][nt][0];
                cs[r0 * 132 + c0 + 1]       = acc[mt][nt][1];
                cs[(r0 + 8) * 132 + c0]     = acc[mt][nt][2];
                cs[(r0 + 8) * 132 + c0 + 1] = acc[mt][nt][3];
            }
    }
    __syncthreads();

    if (mode == 0 || mode == 1) {   // Q (prescaled) / K -> fp16
        int r = tid >> 1, hf = tid & 1;
        size_t ob = (size_t)(m0 + r) * D_ + n0 + hf * 64;
        row64_h(cs + r * 132 + hf * 64, 1, mode ? 1.0f : CEXP,
                (mode ? g_k_f : g_q_f) + ob);
    } else if (mode == 3) {         // O-proj -> fp32 + bias
        int r = tid >> 1, hf = tid & 1;
        float* op = out + (size_t)(m0 + r) * D_ + n0 + hf * 64;
        const float* sp = cs + r * 132 + hf * 64;
        const float* bp = bias + n0 + hf * 64;
#pragma unroll
        for (int g = 0; g < 16; g++) {
            float4 v;
            v.x = sp[g * 4 + 0] + bp[g * 4 + 0];
            v.y = sp[g * 4 + 1] + bp[g * 4 + 1];
            v.z = sp[g * 4 + 2] + bp[g * 4 + 2];
            v.w = sp[g * 4 + 3] + bp[g * 4 + 3];
            *reinterpret_cast<float4*>(op + g * 4) = v;
        }
    } else {                        // V -> fp16 transposed [b,h,d,S]
        int dl = tid >> 1, sh = tid & 1;
        int dg = n0 + dl, hh = dg >> 6, dd = dg & 63, bb = m0 >> 11;
        size_t ob = ((size_t)(bb * 8 + hh) * 64 + dd) * (size_t)S_ + (m0 & 2047) + sh * 64;
        row64_h(cs + (sh * 64) * 132 + dl, 132, 1.0f, g_vt_f + ob);
    }
}

// ------------------------- attention --------------------------------------
// CTA 128q x (b,h); warps = 4 q-bands x 2 kv-halves; warp tile 32q x 32kv.
// kv tiles of 64, 3-stage pipeline, Q reg-resident (prescaled; no FMUL).
// 1-pass QK, 1-pass PV; MMA:LDSM = 4:1. Cross-half O reduce + smem row sums.
#define AQ   0        /* Q 18432 */
#define AK   18432    /* + buf*9216, buf 0..2 */
#define AV   46080    /* + buf*9216, buf 0..2 */
#define ARS  73728    /* rsum float[128] */
#define AOB  74240    /* o cross-half buf: 128 lanes * 68 f32 = 34816 */
#define ASMB 109056

__global__ __launch_bounds__(256) void attn_mma() {
    extern __shared__ char sm[];
    const int tid = threadIdx.x, lane = tid & 31, w = tid >> 5;
    const int qb = w & 3, hv = w >> 2;
    const int qt = blockIdx.x, b = blockIdx.y >> 3, h = blockIdx.y & 7;
    const uint32_t sb = smem_u32(sm);
    float* rsum = reinterpret_cast<float*>(sm + ARS);
    float* obuf = reinterpret_cast<float*>(sm + AOB);

    const size_t qbase = (size_t)(b * S_ + qt * 128) * D_ + h * 64;
    const size_t vbase = (size_t)((b * 8 + h) * 64) * S_;
    if (tid < 128) rsum[tid] = 0.f;

    {   // Q tile fp16, 128 rows x 64 d, pitch 144B
        int r = tid >> 1, sg = (tid & 1) * 4;
        uint32_t d = sb + AQ + r * 144 + sg * 16;
        const size_t so = qbase + (size_t)r * D_ + sg * 8;
#pragma unroll
        for (int j = 0; j < 4; j++) CP_ASYNC(d + j * 16, g_q_f + so + j * 8);
    }
    auto load_kv = [&](int t, int buf) {
        int r = tid >> 2, sg = (tid & 3) * 2;
        {
            uint32_t d = sb + AK + buf * 9216 + r * 144 + sg * 16;
            const size_t so = (size_t)(b * S_ + t * 64 + r) * D_ + h * 64 + sg * 8;
#pragma unroll
            for (int j = 0; j < 2; j++) CP_ASYNC(d + j * 16, g_k_f + so + j * 8);
        }
        {
            uint32_t d = sb + AV + buf * 9216 + r * 144 + sg * 16;
            const size_t so = vbase + (size_t)r * S_ + t * 64 + sg * 8;
#pragma unroll
            for (int j = 0; j < 2; j++) CP_ASYNC(d + j * 16, g_vt_f + so + j * 8);
        }
    };
    load_kv(0, 0); CP_COMMIT();
    load_kv(1, 1); CP_COMMIT();

    uint32_t qf[2][4][4];          // [mt][kk][4]
    float o[2][8][4];              // [mt][d-frag][4]
#pragma unroll
    for (int m = 0; m < 2; m++)
#pragma unroll
        for (int i = 0; i < 8; i++)
#pragma unroll
            for (int j = 0; j < 4; j++) o[m][i][j] = 0.f;
    float rs[2][2] = {{0.f, 0.f}, {0.f, 0.f}};

    const uint32_t rowpat = (uint32_t)(((lane >> 4) & 1) * 8 + (lane & 7)) * 144
                            + ((lane >> 3) & 1) * 16;

    for (int t = 0; t < 32; t++) {
        if (t < 30) CP_WAIT(1); else CP_WAIT(0);
        __syncthreads();
        if (t == 0) {
#pragma unroll
            for (int mt = 0; mt < 2; mt++) {
                uint32_t aa = sb + AQ
                    + (uint32_t)(qb * 32 + mt * 16 + (lane & 15)) * 144
                    + (lane >> 4) * 16;
#pragma unroll
                for (int kk = 0; kk < 4; kk++) ldsm4(qf[mt][kk], aa + kk * 32);
            }
        }
        if (t + 2 < 32) { load_kv(t + 2, (t + 2) % 3); CP_COMMIT(); }
        const uint32_t kb = sb + AK + (t % 3) * 9216 + (uint32_t)(hv * 32) * 144;
        const uint32_t vb = sb + AV + (t % 3) * 9216 + (uint32_t)(hv * 64);

        // S = Q @ K^T : 32q x 32kv per warp
        float s[2][4][4];
#pragma unroll
        for (int m = 0; m < 2; m++)
#pragma unroll
            for (int i = 0; i < 4; i++)
#pragma unroll
                for (int j = 0; j < 4; j++) s[m][i][j] = 0.f;

#pragma unroll
        for (int kk = 0; kk < 4; kk++) {
#pragma unroll
            for (int nt2 = 0; nt2 < 2; nt2++) {
                uint32_t bh[4];
                ldsm4(bh, kb + rowpat + nt2 * 16 * 144 + kk * 32);
#pragma unroll
                for (int mt = 0; mt < 2; mt++) {
                    mma16816h(s[mt][nt2 * 2],     qf[mt][kk], &bh[0]);
                    mma16816h(s[mt][nt2 * 2 + 1], qf[mt][kk], &bh[2]);
                }
            }
        }

        // exp (Q prescaled: no multiply) -> fp16 P frags -> PV
#pragma unroll
        for (int kt = 0; kt < 2; kt++) {
            uint32_t p[2][4];
#pragma unroll
            for (int mt = 0; mt < 2; mt++) {
                float e0 = fast_ex2(s[mt][2*kt][0]),   e1 = fast_ex2(s[mt][2*kt][1]);
                float e2 = fast_ex2(s[mt][2*kt][2]),   e3 = fast_ex2(s[mt][2*kt][3]);
                float e4 = fast_ex2(s[mt][2*kt+1][0]), e5 = fast_ex2(s[mt][2*kt+1][1]);
                float e6 = fast_ex2(s[mt][2*kt+1][2]), e7 = fast_ex2(s[mt][2*kt+1][3]);
                rs[mt][0] += e0 + e1 + e4 + e5;
                rs[mt][1] += e2 + e3 + e6 + e7;
                p[mt][0] = pack2h(e0, e1); p[mt][1] = pack2h(e2, e3);
                p[mt][2] = pack2h(e4, e5); p[mt][3] = pack2h(e6, e7);
            }
#pragma unroll
            for (int dg = 0; dg < 4; dg++) {
                uint32_t vh[4];
                ldsm4(vh, vb + rowpat + dg * 16 * 144 + kt * 32);
#pragma unroll
                for (int mt = 0; mt < 2; mt++) {
                    mma16816h(o[mt][dg * 2],     p[mt], &vh[0]);
                    mma16816h(o[mt][dg * 2 + 1], p[mt], &vh[2]);
                }
            }
        }
    }
    __syncthreads();

    // row sums: reduce over kv within warp, then cross-warp via smem atomics
#pragma unroll
    for (int mt = 0; mt < 2; mt++)
#pragma unroll
        for (int c = 0; c < 2; c++) {
            float v = rs[mt][c];
            v += __shfl_xor_sync(0xffffffffu, v, 1);
            v += __shfl_xor_sync(0xffffffffu, v, 2);
            if ((lane & 3) == 0)
                atomicAdd(&rsum[qb * 32 + mt * 16 + c * 8 + (lane >> 2)], v);
        }

    // cross-half O reduce: hv=1 stores, hv=0 adds
    float* ob = obuf + (size_t)(qb * 32 + lane) * 68;
    if (hv == 1) {
#pragma unroll
        for (int mt = 0; mt < 2; mt++)
#pragma unroll
            for (int dg = 0; dg < 8; dg++)
                *reinterpret_cast<float4*>(ob + mt * 32 + dg * 4) =
                    *reinterpret_cast<const float4*>(o[mt][dg]);
    }
    __syncthreads();
    if (hv == 0) {
#pragma unroll
        for (int mt = 0; mt < 2; mt++) {
#pragma unroll
            for (int dg = 0; dg < 8; dg++) {
                float4 v = *reinterpret_cast<const float4*>(ob + mt * 32 + dg * 4);
                o[mt][dg][0] += v.x; o[mt][dg][1] += v.y;
                o[mt][dg][2] += v.z; o[mt][dg][3] += v.w;
            }
            // normalize + write fp16 att out
#pragma unroll
            for (int c = 0; c < 2; c++) {
                int row = qb * 32 + mt * 16 + c * 8 + (lane >> 2);
                float inv = 1.f / rsum[row];
                size_t r0 = (size_t)(b * S_ + qt * 128 + row) * D_ + h * 64 + 2 * (lane & 3);
#pragma unroll
                for (int dg = 0; dg < 8; dg++)
                    *reinterpret_cast<uint32_t*>(g_att_f + r0 + dg * 8) =
                        pack2h(o[mt][dg][2 * c] * inv, o[mt][dg][2 * c + 1] * inv);
            }
        }
    }
}

// ------------------------- launch -----------------------------------------
extern "C" void kernel_launch(void* const* d_in, const int* in_sizes, int n_in,
                              void* d_out, int out_size) {
    const float* x  = (const float*)d_in[0];
    const float* Wq = (const float*)d_in[1];
    const float* Wk = (const float*)d_in[2];
    const float* Wv = (const float*)d_in[3];
    const float* Wo = (const float*)d_in[4];
    const float* bo = (const float*)d_in[5];
    float* out = (float*)d_out;

    cudaFuncSetAttribute(gemm_mma<true>,  cudaFuncAttributeMaxDynamicSharedMemorySize, GSM);
    cudaFuncSetAttribute(gemm_mma<false>, cudaFuncAttributeMaxDynamicSharedMemorySize, GSM);
    cudaFuncSetAttribute(attn_mma, cudaFuncAttributeMaxDynamicSharedMemorySize, ASMB);

    cvt_x<<<(TOK * D_) / 1024, 256>>>(x);
    cvt_w<<<dim3(16, 16, 4), 256>>>(Wq, Wk, Wv, Wo);
    gemm_mma<true><<<dim3(TOK / 128, D_ / 128, 3), 256, GSM>>>(0, nullptr, nullptr);
    attn_mma<<<dim3(S_ / 128, B_ * 8), 256, ASMB>>>();
    gemm_mma<false><<<dim3(TOK / 128, D_ / 128, 1), 256, GSM>>>(3, bo, out);
}

// round 16
// speedup vs baseline: 1.0646x; 1.0646x over previous
#include <cuda_runtime.h>
#include <cuda_fp16.h>
#include <cstdint>

#define B_ 4
#define S_ 2048
#define D_ 512
#define TOK (B_*S_)

// ------------------------- device scratch ---------------------------------
__device__ __half g_x_fh[TOK*D_], g_x_fl[TOK*D_];     // x fp16 hi/lo
__device__ __half g_w_f[4*D_*D_];                     // W single fp16, [n][k]
__device__ __half g_q_f[TOK*D_];                      // Q fp16, prescaled by log2(e)/8
__device__ __half g_k_f[TOK*D_];                      // K fp16
__device__ __half g_vt_f[TOK*D_];                     // V fp16, [b,h,d,S]
__device__ __half g_att_f[TOK*D_];                    // attn out fp16 single

// ------------------------- PTX helpers ------------------------------------
__device__ __forceinline__ uint32_t smem_u32(const void* p) {
    uint32_t a;
    asm("{ .reg .u64 t; cvta.to.shared.u64 t, %1; cvt.u32.u64 %0, t; }"
        : "=r"(a) : "l"(p));
    return a;
}
#define CP_ASYNC(d, s) asm volatile("cp.async.cg.shared.global [%0], [%1], 16;" :: "r"(d), "l"(s) : "memory")
#define CP_COMMIT()    asm volatile("cp.async.commit_group;" ::: "memory")
#define CP_WAIT(n)     asm volatile("cp.async.wait_group %0;" :: "n"(n) : "memory")

__device__ __forceinline__ void ldsm4(uint32_t* r, uint32_t a) {
    asm volatile("ldmatrix.sync.aligned.m8n8.x4.shared.b16 {%0,%1,%2,%3}, [%4];"
        : "=r"(r[0]), "=r"(r[1]), "=r"(r[2]), "=r"(r[3]) : "r"(a));
}
__device__ __forceinline__ void mma16816h(float* c, const uint32_t* a, const uint32_t* b) {
    asm volatile("mma.sync.aligned.m16n8k16.row.col.f32.f16.f16.f32 "
        "{%0,%1,%2,%3}, {%4,%5,%6,%7}, {%8,%9}, {%0,%1,%2,%3};"
        : "+f"(c[0]), "+f"(c[1]), "+f"(c[2]), "+f"(c[3])
        : "r"(a[0]), "r"(a[1]), "r"(a[2]), "r"(a[3]), "r"(b[0]), "r"(b[1]));
}
__device__ __forceinline__ void split2h(float f0, float f1, uint32_t& h, uint32_t& l) {
    __half h0 = __float2half_rn(f0), h1 = __float2half_rn(f1);
    __half l0 = __float2half_rn(f0 - __half2float(h0));
    __half l1 = __float2half_rn(f1 - __half2float(h1));
    __half2 th = __halves2half2(h0, h1), tl = __halves2half2(l0, l1);
    h = *reinterpret_cast<uint32_t*>(&th);
    l = *reinterpret_cast<uint32_t*>(&tl);
}
__device__ __forceinline__ uint32_t pack2h(float x, float y) {
    __half2 t = __floats2half2_rn(x, y);
    return *reinterpret_cast<uint32_t*>(&t);
}
// exp2 of a float pair, computed in fp16x2 (1 MUFU op), result = fp16 P word
__device__ __forceinline__ uint32_t ex2_h2(float a, float b) {
    uint32_t x = pack2h(a, b), y;
    asm("ex2.approx.f16x2 %0, %1;" : "=r"(y) : "r"(x));
    return y;
}
__device__ __forceinline__ float2 h2f2(uint32_t u) {
    return __half22float2(*reinterpret_cast<__half2*>(&u));
}
// 64 strided floats (scaled) -> 64 fp16
__device__ __forceinline__ void row64_h(const float* src, int stride, float scale, __half* o) {
#pragma unroll
    for (int g = 0; g < 8; g++) {
        uint32_t hh[4];
#pragma unroll
        for (int p = 0; p < 4; p++)
            hh[p] = pack2h(src[(g*8 + p*2) * stride] * scale,
                           src[(g*8 + p*2 + 1) * stride] * scale);
        *reinterpret_cast<uint4*>(o + g*8) = make_uint4(hh[0], hh[1], hh[2], hh[3]);
    }
}

// ------------------------- prep kernels -----------------------------------
__global__ __launch_bounds__(256) void cvt_x(const float* __restrict__ x) {
    size_t i = ((size_t)blockIdx.x * 256 + threadIdx.x) * 4;
    float4 v = *reinterpret_cast<const float4*>(x + i);
    uint32_t h0, l0, h1, l1;
    split2h(v.x, v.y, h0, l0);
    split2h(v.z, v.w, h1, l1);
    *reinterpret_cast<uint2*>(g_x_fh + i) = make_uint2(h0, h1);
    *reinterpret_cast<uint2*>(g_x_fl + i) = make_uint2(l0, l1);
}

__global__ __launch_bounds__(256) void cvt_w(const float* __restrict__ Wq,
                                             const float* __restrict__ Wk,
                                             const float* __restrict__ Wv,
                                             const float* __restrict__ Wo) {
    __shared__ float t[32][33];
    const int z = blockIdx.z;
    const float* W = (z == 0) ? Wq : (z == 1) ? Wk : (z == 2) ? Wv : Wo;
    const int k0 = blockIdx.x * 32, n0 = blockIdx.y * 32;
    const int tx = threadIdx.x & 31, ty = threadIdx.x >> 5;
#pragma unroll
    for (int r = 0; r < 4; r++)
        t[ty + r * 8][tx] = W[(size_t)(k0 + ty + r * 8) * D_ + n0 + tx];
    __syncthreads();
#pragma unroll
    for (int r = 0; r < 4; r++) {
        int nn = ty + r * 8;
        size_t oi = (size_t)z * D_ * D_ + (size_t)(n0 + nn) * D_ + k0 + tx;
        g_w_f[oi] = __float2half_rn(t[tx][nn]);
    }
}

// ------------------------- HMMA GEMM --------------------------------------
// C = A @ W. TWOPASS: A fp16 hi/lo (x). !TWOPASS: A single fp16 (att).
// Block 128x128, warp 64x32, k=32. modes: 0=Q(prescaled) 1=K 2=V(T) 3=O
#define GSM 67584
#define CEXP 0.18033688011112042f   /* log2(e)/8 */

template <bool TWOPASS>
__global__ __launch_bounds__(256, 2) void gemm_mma(int mode_base,
                                                   const float* __restrict__ bias,
                                                   float* __restrict__ out) {
    extern __shared__ char sm[];
    const int tid = threadIdx.x, lane = tid & 31, w = tid >> 5;
    const int wm = w & 1, wn = w >> 1;
    const int mode = mode_base + blockIdx.z;
    const int m0 = blockIdx.x * 128, n0 = blockIdx.y * 128;
    const uint32_t sb = smem_u32(sm);

    const __half* Ah = (TWOPASS ? g_x_fh : g_att_f) + (size_t)m0 * D_;
    const __half* Al = g_x_fl + (size_t)m0 * D_;
    const __half* Bf = g_w_f + (size_t)mode * D_ * D_ + (size_t)n0 * D_;

    float acc[4][4][4];
#pragma unroll
    for (int i = 0; i < 4; i++)
#pragma unroll
        for (int j = 0; j < 4; j++)
#pragma unroll
            for (int k = 0; k < 4; k++) acc[i][j][k] = 0.f;

    const int lr = tid >> 1, half = tid & 1;
    auto load_chunk = [&](int buf, int k0) {
        uint32_t d = sb + buf * 30720 + lr * 80 + half * 32;
        const size_t so = (size_t)lr * D_ + k0 + half * 16;
#pragma unroll
        for (int j = 0; j < 2; j++) {
            CP_ASYNC(d + j * 16, Ah + so + j * 8);
            if (TWOPASS) CP_ASYNC(d + 10240 + j * 16, Al + so + j * 8);
            CP_ASYNC(d + 20480 + j * 16, Bf + so + j * 8);
        }
    };

    load_chunk(0, 0); CP_COMMIT();
    const uint32_t arow = (uint32_t)(wm * 64 + (lane & 15)) * 80 + (lane >> 4) * 16;
    const uint32_t brow = (uint32_t)(wn * 32 + ((lane >> 4) & 1) * 8 + (lane & 7)) * 80
                          + ((lane >> 3) & 1) * 16;

    for (int c = 0; c < 16; c++) {
        if (c < 15) { load_chunk((c + 1) & 1, (c + 1) * 32); CP_COMMIT(); CP_WAIT(1); }
        else CP_WAIT(0);
        __syncthreads();
        const uint32_t base = sb + (c & 1) * 30720;
#pragma unroll
        for (int kk = 0; kk < 2; kk++) {
            uint32_t bh[2][4];
#pragma unroll
            for (int nt2 = 0; nt2 < 2; nt2++)
                ldsm4(bh[nt2], base + 20480 + brow + nt2 * 16 * 80 + kk * 32);
#pragma unroll
            for (int mt = 0; mt < 4; mt++) {
                uint32_t aa = base + arow + mt * 16 * 80 + kk * 32;
                uint32_t ah[4], al[4];
                ldsm4(ah, aa);
                if (TWOPASS) ldsm4(al, aa + 10240);
#pragma unroll
                for (int nt2 = 0; nt2 < 2; nt2++) {
                    mma16816h(acc[mt][nt2 * 2],     ah, &bh[nt2][0]);
                    if (TWOPASS) mma16816h(acc[mt][nt2 * 2], al, &bh[nt2][0]);
                    mma16816h(acc[mt][nt2 * 2 + 1], ah, &bh[nt2][2]);
                    if (TWOPASS) mma16816h(acc[mt][nt2 * 2 + 1], al, &bh[nt2][2]);
                }
            }
        }
        __syncthreads();
    }

    // stage C into smem [128][132] f32
    float* cs = reinterpret_cast<float*>(sm);
    {
        const int rr = wm * 64 + (lane >> 2), cc = wn * 32 + 2 * (lane & 3);
#pragma unroll
        for (int mt = 0; mt < 4; mt++)
#pragma unroll
            for (int nt = 0; nt < 4; nt++) {
                int r0 = rr + mt * 16, c0 = cc + nt * 8;
                cs[r0 * 132 + c0]           = acc[mt][nt][0];
                cs[r0 * 132 + c0 + 1]       = acc[mt][nt][1];
                cs[(r0 + 8) * 132 + c0]     = acc[mt][nt][2];
                cs[(r0 + 8) * 132 + c0 + 1] = acc[mt][nt][3];
            }
    }
    __syncthreads();

    if (mode == 0 || mode == 1) {   // Q (prescaled by CEXP) / K -> fp16
        int r = tid >> 1, hf = tid & 1;
        size_t ob = (size_t)(m0 + r) * D_ + n0 + hf * 64;
        row64_h(cs + r * 132 + hf * 64, 1, mode ? 1.0f : CEXP,
                (mode ? g_k_f : g_q_f) + ob);
    } else if (mode == 3) {         // O-proj -> fp32 + bias
        int r = tid >> 1, hf = tid & 1;
        float* op = out + (size_t)(m0 + r) * D_ + n0 + hf * 64;
        const float* sp = cs + r * 132 + hf * 64;
        const float* bp = bias + n0 + hf * 64;
#pragma unroll
        for (int g = 0; g < 16; g++) {
            float4 v;
            v.x = sp[g * 4 + 0] + bp[g * 4 + 0];
            v.y = sp[g * 4 + 1] + bp[g * 4 + 1];
            v.z = sp[g * 4 + 2] + bp[g * 4 + 2];
            v.w = sp[g * 4 + 3] + bp[g * 4 + 3];
            *reinterpret_cast<float4*>(op + g * 4) = v;
        }
    } else {                        // V -> fp16 transposed [b,h,d,S]
        int dl = tid >> 1, sh = tid & 1;
        int dg = n0 + dl, hh = dg >> 6, dd = dg & 63, bb = m0 >> 11;
        size_t ob = ((size_t)(bb * 8 + hh) * 64 + dd) * (size_t)S_ + (m0 & 2047) + sh * 64;
        row64_h(cs + (sh * 64) * 132 + dl, 132, 1.0f, g_vt_f + ob);
    }
}

// ------------------------- attention --------------------------------------
// R14-proven shape: CTA 128q x (b,h); warp = 16q x 64kv; kv tiles of 64,
// 3-stage pipeline; Q single fp16 register-resident (prescaled -> no FMUL).
// exp via ex2.approx.f16x2 (half the MUFU ops; output IS the P word).
// Row sums from rounded P (self-consistent normalization). 2 CTAs/SM.
#define AQ   0        /* Q 18432 */
#define AK   18432    /* + buf*9216, buf 0..2 */
#define AV   46080    /* + buf*9216, buf 0..2 */
#define ASMB 73728

__global__ __launch_bounds__(256, 2) void attn_mma() {
    extern __shared__ char sm[];
    const int tid = threadIdx.x, lane = tid & 31, w = tid >> 5;
    const int qt = blockIdx.x, b = blockIdx.y >> 3, h = blockIdx.y & 7;
    const uint32_t sb = smem_u32(sm);

    const size_t qbase = (size_t)(b * S_ + qt * 128) * D_ + h * 64;
    const size_t vbase = (size_t)((b * 8 + h) * 64) * S_;

    {   // Q tile single fp16, 128 rows x 64 d, pitch 144B
        int r = tid >> 1, sg = (tid & 1) * 4;
        uint32_t d = sb + AQ + r * 144 + sg * 16;
        const size_t so = qbase + (size_t)r * D_ + sg * 8;
#pragma unroll
        for (int j = 0; j < 4; j++) CP_ASYNC(d + j * 16, g_q_f + so + j * 8);
    }
    auto load_kv = [&](int t, int buf) {
        int r = tid >> 2, sg = (tid & 3) * 2;
        {   // K: 64 rows x 64 d
            uint32_t d = sb + AK + buf * 9216 + r * 144 + sg * 16;
            const size_t so = (size_t)(b * S_ + t * 64 + r) * D_ + h * 64 + sg * 8;
#pragma unroll
            for (int j = 0; j < 2; j++) CP_ASYNC(d + j * 16, g_k_f + so + j * 8);
        }
        {   // V: 64 d rows x 64 kv cols
            uint32_t d = sb + AV + buf * 9216 + r * 144 + sg * 16;
            const size_t so = vbase + (size_t)r * S_ + t * 64 + sg * 8;
#pragma unroll
            for (int j = 0; j < 2; j++) CP_ASYNC(d + j * 16, g_vt_f + so + j * 8);
        }
    };
    load_kv(0, 0); CP_COMMIT();   // group0: Q + kv0
    load_kv(1, 1); CP_COMMIT();   // group1: kv1

    uint32_t qh[4][4];
    float o[8][4];
#pragma unroll
    for (int i = 0; i < 8; i++)
#pragma unroll
        for (int j = 0; j < 4; j++) o[i][j] = 0.f;
    float rs0 = 0.f, rs1 = 0.f;

    const uint32_t qarow = sb + AQ + (uint32_t)(w * 16 + (lane & 15)) * 144 + (lane >> 4) * 16;
    const uint32_t krow  = (uint32_t)(((lane >> 4) & 1) * 8 + (lane & 7)) * 144 + ((lane >> 3) & 1) * 16;

    for (int t = 0; t < 32; t++) {
        if (t < 30) CP_WAIT(1); else CP_WAIT(0);
        __syncthreads();
        if (t == 0) {   // Q fragments -> registers (once)
#pragma unroll
            for (int kk = 0; kk < 4; kk++) ldsm4(qh[kk], qarow + kk * 32);
        }
        if (t + 2 < 32) { load_kv(t + 2, (t + 2) % 3); CP_COMMIT(); }
        const uint32_t kb = sb + AK + (t % 3) * 9216;
        const uint32_t vb = sb + AV + (t % 3) * 9216;

        // S = Q @ K^T : 1-pass fp16 (Q prescaled by log2(e)/8)
        float s[8][4];
#pragma unroll
        for (int i = 0; i < 8; i++)
#pragma unroll
            for (int j = 0; j < 4; j++) s[i][j] = 0.f;

#pragma unroll
        for (int kk = 0; kk < 4; kk++) {
#pragma unroll
            for (int nt2 = 0; nt2 < 4; nt2++) {
                uint32_t ba = kb + krow + nt2 * 16 * 144 + kk * 32;
                uint32_t bh[4];
                ldsm4(bh, ba);
                mma16816h(s[nt2 * 2],     qh[kk], &bh[0]);
                mma16816h(s[nt2 * 2 + 1], qh[kk], &bh[2]);
            }
        }

        // exp2 in f16x2 -> P fragment words; row sums from rounded P
#pragma unroll
        for (int kt = 0; kt < 4; kt++) {
            uint32_t p[4];
            p[0] = ex2_h2(s[2*kt][0],   s[2*kt][1]);
            p[1] = ex2_h2(s[2*kt][2],   s[2*kt][3]);
            p[2] = ex2_h2(s[2*kt+1][0], s[2*kt+1][1]);
            p[3] = ex2_h2(s[2*kt+1][2], s[2*kt+1][3]);
            float2 f0 = h2f2(p[0]), f1 = h2f2(p[1]);
            float2 f2 = h2f2(p[2]), f3 = h2f2(p[3]);
            rs0 += f0.x + f0.y + f2.x + f2.y;
            rs1 += f1.x + f1.y + f3.x + f3.y;
#pragma unroll
            for (int dt2 = 0; dt2 < 4; dt2++) {
                uint32_t va = vb + krow + dt2 * 16 * 144 + kt * 32;
                uint32_t vh[4];
                ldsm4(vh, va);
                mma16816h(o[dt2 * 2],     p, &vh[0]);
                mma16816h(o[dt2 * 2 + 1], p, &vh[2]);
            }
        }
    }

    rs0 += __shfl_xor_sync(0xffffffffu, rs0, 1);
    rs0 += __shfl_xor_sync(0xffffffffu, rs0, 2);
    rs1 += __shfl_xor_sync(0xffffffffu, rs1, 1);
    rs1 += __shfl_xor_sync(0xffffffffu, rs1, 2);
    const float i0 = 1.f / rs0, i1 = 1.f / rs1;

    size_t r0 = (size_t)(b * S_ + qt * 128 + w * 16 + (lane >> 2)) * D_ + h * 64 + 2 * (lane & 3);
#pragma unroll
    for (int dt = 0; dt < 8; dt++) {
        *reinterpret_cast<uint32_t*>(g_att_f + r0 + dt * 8) =
            pack2h(o[dt][0] * i0, o[dt][1] * i0);
        *reinterpret_cast<uint32_t*>(g_att_f + r0 + 8 * D_ + dt * 8) =
            pack2h(o[dt][2] * i1, o[dt][3] * i1);
    }
}

// ------------------------- launch -----------------------------------------
extern "C" void kernel_launch(void* const* d_in, const int* in_sizes, int n_in,
                              void* d_out, int out_size) {
    const float* x  = (const float*)d_in[0];
    const float* Wq = (const float*)d_in[1];
    const float* Wk = (const float*)d_in[2];
    const float* Wv = (const float*)d_in[3];
    const float* Wo = (const float*)d_in[4];
    const float* bo = (const float*)d_in[5];
    float* out = (float*)d_out;

    cudaFuncSetAttribute(gemm_mma<true>,  cudaFuncAttributeMaxDynamicSharedMemorySize, GSM);
    cudaFuncSetAttribute(gemm_mma<false>, cudaFuncAttributeMaxDynamicSharedMemorySize, GSM);
    cudaFuncSetAttribute(attn_mma, cudaFuncAttributeMaxDynamicSharedMemorySize, ASMB);

    cvt_x<<<(TOK * D_) / 1024, 256>>>(x);
    cvt_w<<<dim3(16, 16, 4), 256>>>(Wq, Wk, Wv, Wo);
    gemm_mma<true><<<dim3(TOK / 128, D_ / 128, 3), 256, GSM>>>(0, nullptr, nullptr);
    attn_mma<<<dim3(S_ / 128, B_ * 8), 256, ASMB>>>();
    gemm_mma<false><<<dim3(TOK / 128, D_ / 128, 1), 256, GSM>>>(3, bo, out);
}

// round 17
// speedup vs baseline: 1.2310x; 1.1563x over previous
#include <cuda_runtime.h>
#include <cuda_fp16.h>
#include <cstdint>

#define B_ 4
#define S_ 2048
#define D_ 512
#define TOK (B_*S_)

// ------------------------- device scratch ---------------------------------
__device__ __half g_x_f[TOK*D_];                      // x fp16 single
__device__ __half g_w_f[4*D_*D_];                     // W single fp16, [n][k]
__device__ __half g_q_f[TOK*D_];                      // Q fp16, prescaled by log2(e)/8
__device__ __half g_k_f[TOK*D_];                      // K fp16
__device__ __half g_vt_f[TOK*D_];                     // V fp16, [b,h,d,S]
__device__ __half g_att_f[TOK*D_];                    // attn out fp16 single

// ------------------------- PTX helpers ------------------------------------
__device__ __forceinline__ uint32_t smem_u32(const void* p) {
    uint32_t a;
    asm("{ .reg .u64 t; cvta.to.shared.u64 t, %1; cvt.u32.u64 %0, t; }"
        : "=r"(a) : "l"(p));
    return a;
}
#define CP_ASYNC(d, s) asm volatile("cp.async.cg.shared.global [%0], [%1], 16;" :: "r"(d), "l"(s) : "memory")
#define CP_COMMIT()    asm volatile("cp.async.commit_group;" ::: "memory")
#define CP_WAIT(n)     asm volatile("cp.async.wait_group %0;" :: "n"(n) : "memory")

__device__ __forceinline__ void ldsm4(uint32_t* r, uint32_t a) {
    asm volatile("ldmatrix.sync.aligned.m8n8.x4.shared.b16 {%0,%1,%2,%3}, [%4];"
        : "=r"(r[0]), "=r"(r[1]), "=r"(r[2]), "=r"(r[3]) : "r"(a));
}
__device__ __forceinline__ void mma16816h(float* c, const uint32_t* a, const uint32_t* b) {
    asm volatile("mma.sync.aligned.m16n8k16.row.col.f32.f16.f16.f32 "
        "{%0,%1,%2,%3}, {%4,%5,%6,%7}, {%8,%9}, {%0,%1,%2,%3};"
        : "+f"(c[0]), "+f"(c[1]), "+f"(c[2]), "+f"(c[3])
        : "r"(a[0]), "r"(a[1]), "r"(a[2]), "r"(a[3]), "r"(b[0]), "r"(b[1]));
}
__device__ __forceinline__ uint32_t pack2h(float x, float y) {
    __half2 t = __floats2half2_rn(x, y);
    return *reinterpret_cast<uint32_t*>(&t);
}
// exp2 of a float pair, computed in fp16x2 (1 MUFU op), result = fp16 P word
__device__ __forceinline__ uint32_t ex2_h2(float a, float b) {
    uint32_t x = pack2h(a, b), y;
    asm("ex2.approx.f16x2 %0, %1;" : "=r"(y) : "r"(x));
    return y;
}
__device__ __forceinline__ float2 h2f2(uint32_t u) {
    return __half22float2(*reinterpret_cast<__half2*>(&u));
}
// 64 strided floats (scaled) -> 64 fp16
__device__ __forceinline__ void row64_h(const float* src, int stride, float scale, __half* o) {
#pragma unroll
    for (int g = 0; g < 8; g++) {
        uint32_t hh[4];
#pragma unroll
        for (int p = 0; p < 4; p++)
            hh[p] = pack2h(src[(g*8 + p*2) * stride] * scale,
                           src[(g*8 + p*2 + 1) * stride] * scale);
        *reinterpret_cast<uint4*>(o + g*8) = make_uint4(hh[0], hh[1], hh[2], hh[3]);
    }
}

// ------------------------- prep kernels -----------------------------------
__global__ __launch_bounds__(256) void cvt_x(const float* __restrict__ x) {
    size_t i = ((size_t)blockIdx.x * 256 + threadIdx.x) * 4;
    float4 v = *reinterpret_cast<const float4*>(x + i);
    *reinterpret_cast<uint2*>(g_x_f + i) =
        make_uint2(pack2h(v.x, v.y), pack2h(v.z, v.w));
}

__global__ __launch_bounds__(256) void cvt_w(const float* __restrict__ Wq,
                                             const float* __restrict__ Wk,
                                             const float* __restrict__ Wv,
                                             const float* __restrict__ Wo) {
    __shared__ float t[32][33];
    const int z = blockIdx.z;
    const float* W = (z == 0) ? Wq : (z == 1) ? Wk : (z == 2) ? Wv : Wo;
    const int k0 = blockIdx.x * 32, n0 = blockIdx.y * 32;
    const int tx = threadIdx.x & 31, ty = threadIdx.x >> 5;
#pragma unroll
    for (int r = 0; r < 4; r++)
        t[ty + r * 8][tx] = W[(size_t)(k0 + ty + r * 8) * D_ + n0 + tx];
    __syncthreads();
#pragma unroll
    for (int r = 0; r < 4; r++) {
        int nn = ty + r * 8;
        size_t oi = (size_t)z * D_ * D_ + (size_t)(n0 + nn) * D_ + k0 + tx;
        g_w_f[oi] = __float2half_rn(t[tx][nn]);
    }
}

// ------------------------- HMMA GEMM (fp16 1-pass) -------------------------
// C = A @ W, A single fp16 (x for QKV, att for O-proj).
// Block 128x128, warp 64x32, k=32. modes: 0=Q(prescaled) 1=K 2=V(T) 3=O
#define GSM 67584
#define CEXP 0.18033688011112042f   /* log2(e)/8 */

__global__ __launch_bounds__(256, 2) void gemm_mma(int mode_base,
                                                   const float* __restrict__ bias,
                                                   float* __restrict__ out) {
    extern __shared__ char sm[];
    const int tid = threadIdx.x, lane = tid & 31, w = tid >> 5;
    const int wm = w & 1, wn = w >> 1;
    const int mode = mode_base + blockIdx.z;
    const int m0 = blockIdx.x * 128, n0 = blockIdx.y * 128;
    const uint32_t sb = smem_u32(sm);

    const __half* Af = ((mode < 3) ? g_x_f : g_att_f) + (size_t)m0 * D_;
    const __half* Bf = g_w_f + (size_t)mode * D_ * D_ + (size_t)n0 * D_;

    float acc[4][4][4];
#pragma unroll
    for (int i = 0; i < 4; i++)
#pragma unroll
        for (int j = 0; j < 4; j++)
#pragma unroll
            for (int k = 0; k < 4; k++) acc[i][j][k] = 0.f;

    const int lr = tid >> 1, half = tid & 1;
    auto load_chunk = [&](int buf, int k0) {
        uint32_t d = sb + buf * 20480 + lr * 80 + half * 32;
        const size_t so = (size_t)lr * D_ + k0 + half * 16;
#pragma unroll
        for (int j = 0; j < 2; j++) {
            CP_ASYNC(d + j * 16,         Af + so + j * 8);
            CP_ASYNC(d + 10240 + j * 16, Bf + so + j * 8);
        }
    };

    load_chunk(0, 0); CP_COMMIT();
    const uint32_t arow = (uint32_t)(wm * 64 + (lane & 15)) * 80 + (lane >> 4) * 16;
    const uint32_t brow = (uint32_t)(wn * 32 + ((lane >> 4) & 1) * 8 + (lane & 7)) * 80
                          + ((lane >> 3) & 1) * 16;

    for (int c = 0; c < 16; c++) {
        if (c < 15) { load_chunk((c + 1) & 1, (c + 1) * 32); CP_COMMIT(); CP_WAIT(1); }
        else CP_WAIT(0);
        __syncthreads();
        const uint32_t base = sb + (c & 1) * 20480;
#pragma unroll
        for (int kk = 0; kk < 2; kk++) {
            uint32_t bh[2][4];
#pragma unroll
            for (int nt2 = 0; nt2 < 2; nt2++)
                ldsm4(bh[nt2], base + 10240 + brow + nt2 * 16 * 80 + kk * 32);
#pragma unroll
            for (int mt = 0; mt < 4; mt++) {
                uint32_t ah[4];
                ldsm4(ah, base + arow + mt * 16 * 80 + kk * 32);
#pragma unroll
                for (int nt2 = 0; nt2 < 2; nt2++) {
                    mma16816h(acc[mt][nt2 * 2],     ah, &bh[nt2][0]);
                    mma16816h(acc[mt][nt2 * 2 + 1], ah, &bh[nt2][2]);
                }
            }
        }
        __syncthreads();
    }

    // stage C into smem [128][132] f32
    float* cs = reinterpret_cast<float*>(sm);
    {
        const int rr = wm * 64 + (lane >> 2), cc = wn * 32 + 2 * (lane & 3);
#pragma unroll
        for (int mt = 0; mt < 4; mt++)
#pragma unroll
            for (int nt = 0; nt < 4; nt++) {
                int r0 = rr + mt * 16, c0 = cc + nt * 8;
                cs[r0 * 132 + c0]           = acc[mt][nt][0];
                cs[r0 * 132 + c0 + 1]       = acc[mt][nt][1];
                cs[(r0 + 8) * 132 + c0]     = acc[mt][nt][2];
                cs[(r0 + 8) * 132 + c0 + 1] = acc[mt][nt][3];
            }
    }
    __syncthreads();

    if (mode == 0 || mode == 1) {   // Q (prescaled by CEXP) / K -> fp16
        int r = tid >> 1, hf = tid & 1;
        size_t ob = (size_t)(m0 + r) * D_ + n0 + hf * 64;
        row64_h(cs + r * 132 + hf * 64, 1, mode ? 1.0f : CEXP,
                (mode ? g_k_f : g_q_f) + ob);
    } else if (mode == 3) {         // O-proj -> fp32 + bias
        int r = tid >> 1, hf = tid & 1;
        float* op = out + (size_t)(m0 + r) * D_ + n0 + hf * 64;
        const float* sp = cs + r * 132 + hf * 64;
        const float* bp = bias + n0 + hf * 64;
#pragma unroll
        for (int g = 0; g < 16; g++) {
            float4 v;
            v.x = sp[g * 4 + 0] + bp[g * 4 + 0];
            v.y = sp[g * 4 + 1] + bp[g * 4 + 1];
            v.z = sp[g * 4 + 2] + bp[g * 4 + 2];
            v.w = sp[g * 4 + 3] + bp[g * 4 + 3];
            *reinterpret_cast<float4*>(op + g * 4) = v;
        }
    } else {                        // V -> fp16 transposed [b,h,d,S]
        int dl = tid >> 1, sh = tid & 1;
        int dg = n0 + dl, hh = dg >> 6, dd = dg & 63, bb = m0 >> 11;
        size_t ob = ((size_t)(bb * 8 + hh) * 64 + dd) * (size_t)S_ + (m0 & 2047) + sh * 64;
        row64_h(cs + (sh * 64) * 132 + dl, 132, 1.0f, g_vt_f + ob);
    }
}

// ------------------------- attention --------------------------------------
// Proven shape: CTA 128q x (b,h); warp = 16q x 64kv; kv tiles of 64,
// 3-stage pipeline; Q single fp16 register-resident (prescaled -> no FMUL).
// exp via ex2.approx.f16x2; row sums from rounded P. 2 CTAs/SM.
#define AQ   0        /* Q 18432 */
#define AK   18432    /* + buf*9216, buf 0..2 */
#define AV   46080    /* + buf*9216, buf 0..2 */
#define ASMB 73728

__global__ __launch_bounds__(256, 2) void attn_mma() {
    extern __shared__ char sm[];
    const int tid = threadIdx.x, lane = tid & 31, w = tid >> 5;
    const int qt = blockIdx.x, b = blockIdx.y >> 3, h = blockIdx.y & 7;
    const uint32_t sb = smem_u32(sm);

    const size_t qbase = (size_t)(b * S_ + qt * 128) * D_ + h * 64;
    const size_t vbase = (size_t)((b * 8 + h) * 64) * S_;

    {   // Q tile single fp16, 128 rows x 64 d, pitch 144B
        int r = tid >> 1, sg = (tid & 1) * 4;
        uint32_t d = sb + AQ + r * 144 + sg * 16;
        const size_t so = qbase + (size_t)r * D_ + sg * 8;
#pragma unroll
        for (int j = 0; j < 4; j++) CP_ASYNC(d + j * 16, g_q_f + so + j * 8);
    }
    auto load_kv = [&](int t, int buf) {
        int r = tid >> 2, sg = (tid & 3) * 2;
        {   // K: 64 rows x 64 d
            uint32_t d = sb + AK + buf * 9216 + r * 144 + sg * 16;
            const size_t so = (size_t)(b * S_ + t * 64 + r) * D_ + h * 64 + sg * 8;
#pragma unroll
            for (int j = 0; j < 2; j++) CP_ASYNC(d + j * 16, g_k_f + so + j * 8);
        }
        {   // V: 64 d rows x 64 kv cols
            uint32_t d = sb + AV + buf * 9216 + r * 144 + sg * 16;
            const size_t so = vbase + (size_t)r * S_ + t * 64 + sg * 8;
#pragma unroll
            for (int j = 0; j < 2; j++) CP_ASYNC(d + j * 16, g_vt_f + so + j * 8);
        }
    };
    load_kv(0, 0); CP_COMMIT();   // group0: Q + kv0
    load_kv(1, 1); CP_COMMIT();   // group1: kv1

    uint32_t qh[4][4];
    float o[8][4];
#pragma unroll
    for (int i = 0; i < 8; i++)
#pragma unroll
        for (int j = 0; j < 4; j++) o[i][j] = 0.f;
    float rs0 = 0.f, rs1 = 0.f;

    const uint32_t qarow = sb + AQ + (uint32_t)(w * 16 + (lane & 15)) * 144 + (lane >> 4) * 16;
    const uint32_t krow  = (uint32_t)(((lane >> 4) & 1) * 8 + (lane & 7)) * 144 + ((lane >> 3) & 1) * 16;

    for (int t = 0; t < 32; t++) {
        if (t < 30) CP_WAIT(1); else CP_WAIT(0);
        __syncthreads();
        if (t == 0) {   // Q fragments -> registers (once)
#pragma unroll
            for (int kk = 0; kk < 4; kk++) ldsm4(qh[kk], qarow + kk * 32);
        }
        if (t + 2 < 32) { load_kv(t + 2, (t + 2) % 3); CP_COMMIT(); }
        const uint32_t kb = sb + AK + (t % 3) * 9216;
        const uint32_t vb = sb + AV + (t % 3) * 9216;

        // S = Q @ K^T : 1-pass fp16 (Q prescaled by log2(e)/8)
        float s[8][4];
#pragma unroll
        for (int i = 0; i < 8; i++)
#pragma unroll
            for (int j = 0; j < 4; j++) s[i][j] = 0.f;

#pragma unroll
        for (int kk = 0; kk < 4; kk++) {
#pragma unroll
            for (int nt2 = 0; nt2 < 4; nt2++) {
                uint32_t ba = kb + krow + nt2 * 16 * 144 + kk * 32;
                uint32_t bh[4];
                ldsm4(bh, ba);
                mma16816h(s[nt2 * 2],     qh[kk], &bh[0]);
                mma16816h(s[nt2 * 2 + 1], qh[kk], &bh[2]);
            }
        }

        // exp2 in f16x2 -> P fragment words; row sums from rounded P
#pragma unroll
        for (int kt = 0; kt < 4; kt++) {
            uint32_t p[4];
            p[0] = ex2_h2(s[2*kt][0],   s[2*kt][1]);
            p[1] = ex2_h2(s[2*kt][2],   s[2*kt][3]);
            p[2] = ex2_h2(s[2*kt+1][0], s[2*kt+1][1]);
            p[3] = ex2_h2(s[2*kt+1][2], s[2*kt+1][3]);
            float2 f0 = h2f2(p[0]), f1 = h2f2(p[1]);
            float2 f2 = h2f2(p[2]), f3 = h2f2(p[3]);
            rs0 += f0.x + f0.y + f2.x + f2.y;
            rs1 += f1.x + f1.y + f3.x + f3.y;
#pragma unroll
            for (int dt2 = 0; dt2 < 4; dt2++) {
                uint32_t va = vb + krow + dt2 * 16 * 144 + kt * 32;
                uint32_t vh[4];
                ldsm4(vh, va);
                mma16816h(o[dt2 * 2],     p, &vh[0]);
                mma16816h(o[dt2 * 2 + 1], p, &vh[2]);
            }
        }
    }

    rs0 += __shfl_xor_sync(0xffffffffu, rs0, 1);
    rs0 += __shfl_xor_sync(0xffffffffu, rs0, 2);
    rs1 += __shfl_xor_sync(0xffffffffu, rs1, 1);
    rs1 += __shfl_xor_sync(0xffffffffu, rs1, 2);
    const float i0 = 1.f / rs0, i1 = 1.f / rs1;

    size_t r0 = (size_t)(b * S_ + qt * 128 + w * 16 + (lane >> 2)) * D_ + h * 64 + 2 * (lane & 3);
#pragma unroll
    for (int dt = 0; dt < 8; dt++) {
        *reinterpret_cast<uint32_t*>(g_att_f + r0 + dt * 8) =
            pack2h(o[dt][0] * i0, o[dt][1] * i0);
        *reinterpret_cast<uint32_t*>(g_att_f + r0 + 8 * D_ + dt * 8) =
            pack2h(o[dt][2] * i1, o[dt][3] * i1);
    }
}

// ------------------------- launch -----------------------------------------
extern "C" void kernel_launch(void* const* d_in, const int* in_sizes, int n_in,
                              void* d_out, int out_size) {
    const float* x  = (const float*)d_in[0];
    const float* Wq = (const float*)d_in[1];
    const float* Wk = (const float*)d_in[2];
    const float* Wv = (const float*)d_in[3];
    const float* Wo = (const float*)d_in[4];
    const float* bo = (const float*)d_in[5];
    float* out = (float*)d_out;

    cudaFuncSetAttribute(gemm_mma, cudaFuncAttributeMaxDynamicSharedMemorySize, GSM);
    cudaFuncSetAttribute(attn_mma, cudaFuncAttributeMaxDynamicSharedMemorySize, ASMB);

    cvt_x<<<(TOK * D_) / 1024, 256>>>(x);
    cvt_w<<<dim3(16, 16, 4), 256>>>(Wq, Wk, Wv, Wo);
    gemm_mma<<<dim3(TOK / 128, D_ / 128, 3), 256, GSM>>>(0, nullptr, nullptr);  // Q,K,V
    attn_mma<<<dim3(S_ / 128, B_ * 8), 256, ASMB>>>();
    gemm_mma<<<dim3(TOK / 128, D_ / 128, 1), 256, GSM>>>(3, bo, out);           // O-proj
}